// round 16
// baseline (speedup 1.0000x reference)
#include <cuda_runtime.h>
#include <cuda_fp16.h>
#include <cuda_bf16.h>
#include <cuda_fp8.h>
#include <cstdint>

#define TOK   512
#define HD    2880
#define ID    2880
#define NEXP  8
#define ATOT  1024
#define KD    2880
#define GUN   5760

#define MT    192
#define NT    80
#define KTLE  64
#define NKT   (KD / KTLE)     // 45
#define ASTR  72
#define BSTR  72
#define A_ELEMS (MT * ASTR)   // 13824 halves
#define B_EL    (NT * BSTR)   // 5760 halves per plane

__device__ __align__(16) __nv_bfloat16 g_xdq[TOK * HD];
__device__ __align__(16) __half        g_inter[ATOT * ID];
__device__ __align__(16) float         g_mid[ATOT * ID];
__device__ __align__(16) float         g_y[ATOT * HD];
__device__ int g_list[ATOT];
__device__ int g_pos[ATOT];
__device__ int g_start[NEXP];
__device__ int g_cnt[NEXP];

__device__ __forceinline__ float ceil_pow2_scale(float ds) {
    unsigned i = __float_as_uint(ds);
    i = (i + 0x7FFFFFu) & 0x7F800000u;
    float r = __uint_as_float(i);
    return (r == 0.0f) ? 1.17549435e-38f : r;
}

__device__ __forceinline__ float fp8_qdq(float v, float dsr) {
    float inv = __uint_as_float(0x7F000000u - __float_as_uint(dsr));
    float q = v * inv;
    q = fminf(fmaxf(q, -448.0f), 448.0f);
    __nv_fp8_storage_t s = __nv_cvt_float_to_fp8(q, __NV_SATFINITE, __NV_E4M3);
    __half_raw hr = __nv_cvt_fp8_to_halfraw(s, __NV_E4M3);
    return __half2float(*reinterpret_cast<__half*>(&hr)) * dsr;
}

#define LDSM4(R, ADDR) asm volatile( \
    "ldmatrix.sync.aligned.m8n8.x4.shared.b16 {%0,%1,%2,%3},[%4];" \
    : "=r"((R)[0]), "=r"((R)[1]), "=r"((R)[2]), "=r"((R)[3]) : "r"(ADDR))

#define LDSM2(R, ADDR) asm volatile( \
    "ldmatrix.sync.aligned.m8n8.x2.shared.b16 {%0,%1},[%2];" \
    : "=r"((R)[0]), "=r"((R)[1]) : "r"(ADDR))

#define MMA_IMPL(TYSTR, C, A, B0, B1) asm volatile( \
    "mma.sync.aligned.m16n8k16.row.col.f32." TYSTR ".f32 " \
    "{%0,%1,%2,%3},{%4,%5,%6,%7},{%8,%9},{%0,%1,%2,%3};" \
    : "+f"((C)[0]), "+f"((C)[1]), "+f"((C)[2]), "+f"((C)[3]) \
    : "r"((A)[0]), "r"((A)[1]), "r"((A)[2]), "r"((A)[3]), "r"(B0), "r"(B1))

#define CP_ASYNC16(DST, SRC) asm volatile( \
    "cp.async.cg.shared.global [%0],[%1],16;" :: "r"(DST), "l"(SRC))
#define CP_COMMIT asm volatile("cp.async.commit_group;")
#define CP_WAIT0  asm volatile("cp.async.wait_group 0;" ::: "memory")

// blocks 0..719: quantize x (8 values/thread, 4 lanes per 32-block)
// block 720: routing (256 threads, 4 assignments each)
__global__ void quantx_route_kernel(const float* __restrict__ x,
                                    const int* __restrict__ ridx) {
    if (blockIdx.x < TOK * HD / 2048) {
        int idx = blockIdx.x * 256 + threadIdx.x;
        float4 v0 = *reinterpret_cast<const float4*>(x + (size_t)idx * 8);
        float4 v1 = *reinterpret_cast<const float4*>(x + (size_t)idx * 8 + 4);
        float m = fmaxf(fmaxf(fmaxf(fabsf(v0.x), fabsf(v0.y)), fmaxf(fabsf(v0.z), fabsf(v0.w))),
                        fmaxf(fmaxf(fabsf(v1.x), fabsf(v1.y)), fmaxf(fabsf(v1.z), fabsf(v1.w))));
        #pragma unroll
        for (int o = 2; o; o >>= 1) m = fmaxf(m, __shfl_xor_sync(0xffffffffu, m, o));
        float dsr = ceil_pow2_scale(m / 448.0f);
        __nv_bfloat162 p0, p1, p2, p3;
        p0.x = __float2bfloat16_rn(fp8_qdq(v0.x, dsr));
        p0.y = __float2bfloat16_rn(fp8_qdq(v0.y, dsr));
        p1.x = __float2bfloat16_rn(fp8_qdq(v0.z, dsr));
        p1.y = __float2bfloat16_rn(fp8_qdq(v0.w, dsr));
        p2.x = __float2bfloat16_rn(fp8_qdq(v1.x, dsr));
        p2.y = __float2bfloat16_rn(fp8_qdq(v1.y, dsr));
        p3.x = __float2bfloat16_rn(fp8_qdq(v1.z, dsr));
        p3.y = __float2bfloat16_rn(fp8_qdq(v1.w, dsr));
        *reinterpret_cast<uint4*>((uint16_t*)g_xdq + (size_t)idx * 8) =
            make_uint4(*reinterpret_cast<uint32_t*>(&p0), *reinterpret_cast<uint32_t*>(&p1),
                       *reinterpret_cast<uint32_t*>(&p2), *reinterpret_cast<uint32_t*>(&p3));
    } else {
        __shared__ int cnt[NEXP], off[NEXP];
        int t = threadIdx.x;
        if (t < NEXP) cnt[t] = 0;
        __syncthreads();
        int e[4];
        #pragma unroll
        for (int k = 0; k < 4; k++) {
            e[k] = ridx[t + k * 256];
            atomicAdd(&cnt[e[k]], 1);
        }
        __syncthreads();
        if (t == 0) {
            int s = 0;
            for (int i = 0; i < NEXP; i++) {
                g_start[i] = s; off[i] = s; g_cnt[i] = cnt[i]; s += cnt[i];
            }
        }
        __syncthreads();
        #pragma unroll
        for (int k = 0; k < 4; k++) {
            int p = atomicAdd(&off[e[k]], 1);
            g_list[p] = t + k * 256;
            g_pos[t + k * 256] = p;
        }
    }
}

// 8 values/thread, 4 lanes per 32-block; bit-exact qdq
__global__ void requant_kernel() {
    int idx = blockIdx.x * 256 + threadIdx.x;
    float4 v0 = *reinterpret_cast<const float4*>(g_mid + (size_t)idx * 8);
    float4 v1 = *reinterpret_cast<const float4*>(g_mid + (size_t)idx * 8 + 4);
    float m = fmaxf(fmaxf(fmaxf(fabsf(v0.x), fabsf(v0.y)), fmaxf(fabsf(v0.z), fabsf(v0.w))),
                    fmaxf(fmaxf(fabsf(v1.x), fabsf(v1.y)), fmaxf(fabsf(v1.z), fabsf(v1.w))));
    #pragma unroll
    for (int o = 2; o; o >>= 1) m = fmaxf(m, __shfl_xor_sync(0xffffffffu, m, o));
    float dsr = ceil_pow2_scale(m / 448.0f);
    __half2 p0, p1, p2, p3;
    p0.x = __float2half_rn(fp8_qdq(v0.x, dsr));
    p0.y = __float2half_rn(fp8_qdq(v0.y, dsr));
    p1.x = __float2half_rn(fp8_qdq(v0.z, dsr));
    p1.y = __float2half_rn(fp8_qdq(v0.w, dsr));
    p2.x = __float2half_rn(fp8_qdq(v1.x, dsr));
    p2.y = __float2half_rn(fp8_qdq(v1.y, dsr));
    p3.x = __float2half_rn(fp8_qdq(v1.z, dsr));
    p3.y = __float2half_rn(fp8_qdq(v1.w, dsr));
    *reinterpret_cast<uint4*>((uint16_t*)g_inter + (size_t)idx * 8) =
        make_uint4(*reinterpret_cast<uint32_t*>(&p0), *reinterpret_cast<uint32_t*>(&p1),
                   *reinterpret_cast<uint32_t*>(&p2), *reinterpret_cast<uint32_t*>(&p3));
}

// PHASE 0: gate_up (bf16 hi/lo planes) + swiglu -> g_mid (fp32)
// PHASE 1: down (fp16) + bias -> g_y
// Warp grid 4M x 2N; warp tile 48 x 40; NT=80, occ 2.
template<int PHASE>
__global__ void __launch_bounds__(256, 2) gemm_kernel(
    const float* __restrict__ Wg, const float* __restrict__ biasg)
{
    constexpr int NTOT = (PHASE == 0) ? GUN : HD;
    constexpr int NPL  = (PHASE == 0) ? 2 : 1;
    constexpr int STG  = A_ELEMS + NPL * B_EL;
    const int nt = blockIdx.x, mt = blockIdx.y, e = blockIdx.z;
    const int cnt = g_cnt[e];
    if (mt * MT >= cnt) return;
    const int start = g_start[e];
    const int n0 = nt * NT;
    const int tid = threadIdx.x;
    const int lane = tid & 31, wid = tid >> 5;
    const int wm = wid & 3, wn = wid >> 2;

    extern __shared__ __align__(16) char smem_raw[];
    uint16_t* sm = (uint16_t*)smem_raw;
    uint32_t smemBase = (uint32_t)__cvta_generic_to_shared(sm);
    __shared__ int s_a[MT];

    if (tid < MT) {
        int p = start + mt * MT + tid; if (p > ATOT - 1) p = ATOT - 1;
        s_a[tid] = (PHASE == 0) ? (g_list[p] >> 1) : p;
    }
    __syncthreads();

    const uint16_t* srcA = (PHASE == 0) ? (const uint16_t*)g_xdq
                                        : (const uint16_t*)g_inter;
    const float* W = Wg + (size_t)e * NTOT * KD + (size_t)n0 * KD;

    const int aLdOff = (lane & 15) * ASTR + (lane >> 4) * 8 + wm * 48 * ASTR;
    const int bLd16 = ((lane & 7) + ((lane & 16) ? 8 : 0)) * BSTR +
                      ((lane & 8) ? 8 : 0) + wn * 40 * BSTR;
    const int bLd8  = (lane & 7) * BSTR + ((lane & 8) ? 8 : 0) +
                      (wn * 40 + 32) * BSTR;

    float acc[3][5][4];
    #pragma unroll
    for (int i = 0; i < 3; i++)
        #pragma unroll
        for (int j = 0; j < 5; j++)
            #pragma unroll
            for (int k = 0; k < 4; k++) acc[i][j][k] = 0.0f;

    float4 breg[5];
    auto loadB = [&](int kt) {
        #pragma unroll
        for (int j = 0; j < 5; j++) {
            int chunk = tid + j * 256;
            breg[j] = *reinterpret_cast<const float4*>(
                W + (size_t)(chunk >> 4) * KD + kt * KTLE + (chunk & 15) * 4);
        }
    };
    auto cpA = [&](int st, int kt) {
        uint32_t so = smemBase + (uint32_t)(st * STG) * 2;
        #pragma unroll
        for (int i = 0; i < 6; i++) {
            int chunk = tid + i * 256;
            int row = chunk >> 3, c16 = chunk & 7;
            const uint16_t* src = srcA + (size_t)s_a[row] * KD + c16 * 8 + kt * KTLE;
            CP_ASYNC16(so + (uint32_t)(row * ASTR + c16 * 8) * 2, src);
        }
        CP_COMMIT;
    };
    auto stsB = [&](int st) {
        uint16_t* bh = sm + st * STG + A_ELEMS;
        #pragma unroll
        for (int j = 0; j < 5; j++) {
            int chunk = tid + j * 256;
            int off = (chunk >> 4) * BSTR + (chunk & 15) * 4;
            float f[4] = {breg[j].x, breg[j].y, breg[j].z, breg[j].w};
            if constexpr (PHASE == 0) {
                uint32_t hv[2], lv[2];
                #pragma unroll
                for (int q = 0; q < 2; q++) {
                    __nv_bfloat16 h0 = __float2bfloat16_rn(f[2 * q]);
                    __nv_bfloat16 h1 = __float2bfloat16_rn(f[2 * q + 1]);
                    __nv_bfloat162 hh; hh.x = h0; hh.y = h1;
                    __nv_bfloat162 ll = __floats2bfloat162_rn(
                        f[2 * q]     - __bfloat162float(h0),
                        f[2 * q + 1] - __bfloat162float(h1));
                    hv[q] = *reinterpret_cast<uint32_t*>(&hh);
                    lv[q] = *reinterpret_cast<uint32_t*>(&ll);
                }
                *reinterpret_cast<uint2*>(bh + off)        = make_uint2(hv[0], hv[1]);
                *reinterpret_cast<uint2*>(bh + B_EL + off) = make_uint2(lv[0], lv[1]);
            } else {
                __half2 h0 = __floats2half2_rn(f[0], f[1]);
                __half2 h1 = __floats2half2_rn(f[2], f[3]);
                *reinterpret_cast<uint2*>(bh + off) =
                    make_uint2(*reinterpret_cast<uint32_t*>(&h0),
                               *reinterpret_cast<uint32_t*>(&h1));
            }
        }
    };
    auto compute = [&](int st) {
        uint32_t aB = smemBase + (uint32_t)(st * STG) * 2;
        uint32_t bB = aB + A_ELEMS * 2;
        #pragma unroll
        for (int ks = 0; ks < 4; ks++) {
            uint32_t ar[3][4], b4[2][4], b2[2];
            #pragma unroll
            for (int mf = 0; mf < 3; mf++)
                LDSM4(ar[mf], aB + (uint32_t)(aLdOff + mf * 16 * ASTR + ks * 16) * 2);
            LDSM4(b4[0], bB + (uint32_t)(bLd16 + ks * 16) * 2);
            LDSM4(b4[1], bB + (uint32_t)(bLd16 + 16 * BSTR + ks * 16) * 2);
            LDSM2(b2,    bB + (uint32_t)(bLd8 + ks * 16) * 2);
            #pragma unroll
            for (int mf = 0; mf < 3; mf++) {
                #pragma unroll
                for (int nf = 0; nf < 4; nf++) {
                    int ng = nf >> 1, pr = nf & 1;
                    if constexpr (PHASE == 0)
                        MMA_IMPL("bf16.bf16", acc[mf][nf], ar[mf], b4[ng][2*pr], b4[ng][2*pr+1]);
                    else
                        MMA_IMPL("f16.f16",   acc[mf][nf], ar[mf], b4[ng][2*pr], b4[ng][2*pr+1]);
                }
                if constexpr (PHASE == 0)
                    MMA_IMPL("bf16.bf16", acc[mf][4], ar[mf], b2[0], b2[1]);
                else
                    MMA_IMPL("f16.f16",   acc[mf][4], ar[mf], b2[0], b2[1]);
            }
            if constexpr (PHASE == 0) {
                uint32_t lB = bB + B_EL * 2;
                LDSM4(b4[0], lB + (uint32_t)(bLd16 + ks * 16) * 2);
                LDSM4(b4[1], lB + (uint32_t)(bLd16 + 16 * BSTR + ks * 16) * 2);
                LDSM2(b2,    lB + (uint32_t)(bLd8 + ks * 16) * 2);
                #pragma unroll
                for (int mf = 0; mf < 3; mf++) {
                    #pragma unroll
                    for (int nf = 0; nf < 4; nf++) {
                        int ng = nf >> 1, pr = nf & 1;
                        MMA_IMPL("bf16.bf16", acc[mf][nf], ar[mf], b4[ng][2*pr], b4[ng][2*pr+1]);
                    }
                    MMA_IMPL("bf16.bf16", acc[mf][4], ar[mf], b2[0], b2[1]);
                }
            }
        }
    };

    loadB(0);
    cpA(0, 0);
    stsB(0);
    CP_WAIT0;
    __syncthreads();
    for (int kt = 0; kt < NKT; kt++) {
        int nk = kt + 1;
        if (nk < NKT) { loadB(nk); cpA(nk & 1, nk); }
        compute(kt & 1);
        if (nk < NKT) { stsB(nk & 1); CP_WAIT0; }
        __syncthreads();
    }

    const int remain = cnt - mt * MT;
    const float* bias = biasg + (size_t)e * NTOT;

    if constexpr (PHASE == 0) {
        #pragma unroll
        for (int mf = 0; mf < 3; mf++)
            #pragma unroll
            for (int nf = 0; nf < 5; nf++) {
                int gl = wn * 40 + nf * 8 + 2 * (lane & 3);
                float bg = bias[n0 + gl], bu = bias[n0 + gl + 1];
                int icol = nt * 40 + wn * 20 + nf * 4 + (lane & 3);
                #pragma unroll
                for (int h = 0; h < 2; h++) {
                    int r = wm * 48 + mf * 16 + (lane >> 2) + h * 8;
                    if (r < remain) {
                        float gate = acc[mf][nf][2 * h] + bg;
                        float up   = acc[mf][nf][2 * h + 1] + bu;
                        gate = fminf(gate, 7.0f);
                        up = fminf(fmaxf(up, -7.0f), 7.0f);
                        float sig = 1.0f / (1.0f + expf(-1.702f * gate));
                        g_mid[(size_t)(start + mt * MT + r) * ID + icol] =
                            gate * sig * (up + 1.0f);
                    }
                }
            }
    } else {
        #pragma unroll
        for (int mf = 0; mf < 3; mf++)
            #pragma unroll
            for (int nf = 0; nf < 5; nf++) {
                int col = n0 + wn * 40 + nf * 8 + 2 * (lane & 3);
                float b0 = bias[col], b1 = bias[col + 1];
                #pragma unroll
                for (int h = 0; h < 2; h++) {
                    int r = wm * 48 + mf * 16 + (lane >> 2) + h * 8;
                    if (r < remain) {
                        float* dst = g_y + (size_t)(start + mt * MT + r) * HD + col;
                        dst[0] = acc[mf][nf][2 * h]     + b0;
                        dst[1] = acc[mf][nf][2 * h + 1] + b1;
                    }
                }
            }
    }
}

// float4 combine: 4 consecutive columns per thread
__global__ void combine_kernel(const float* __restrict__ rw, float* __restrict__ out) {
    int idx = blockIdx.x * 256 + threadIdx.x;   // over TOK * (HD/4)
    int t = idx / (HD / 4);
    int c4 = (idx % (HD / 4)) * 4;
    int a0 = 2 * t, a1 = 2 * t + 1;
    float w0 = rw[a0], w1 = rw[a1];
    const float4 v0 = *reinterpret_cast<const float4*>(
        g_y + (size_t)g_pos[a0] * HD + c4);
    const float4 v1 = *reinterpret_cast<const float4*>(
        g_y + (size_t)g_pos[a1] * HD + c4);
    float4 o;
    o.x = w0 * v0.x + w1 * v1.x;
    o.y = w0 * v0.y + w1 * v1.y;
    o.z = w0 * v0.z + w1 * v1.z;
    o.w = w0 * v0.w + w1 * v1.w;
    *reinterpret_cast<float4*>(out + (size_t)t * HD + c4) = o;
}

#define SMEM0 (2 * (A_ELEMS + 2 * B_EL) * 2)   // 101376
#define SMEM1 (2 * (A_ELEMS + 1 * B_EL) * 2)   // 78336

extern "C" void kernel_launch(void* const* d_in, const int* in_sizes, int n_in,
                              void* d_out, int out_size) {
    const float* x    = (const float*)d_in[0];
    const int*   ridx = (const int*)d_in[1];
    const float* rw   = (const float*)d_in[2];
    const float* wgu  = (const float*)d_in[3];
    const float* bgu  = (const float*)d_in[4];
    const float* wdn  = (const float*)d_in[5];
    const float* bdn  = (const float*)d_in[6];
    float* out = (float*)d_out;

    cudaFuncSetAttribute(gemm_kernel<0>, cudaFuncAttributeMaxDynamicSharedMemorySize, SMEM0);
    cudaFuncSetAttribute(gemm_kernel<1>, cudaFuncAttributeMaxDynamicSharedMemorySize, SMEM1);

    quantx_route_kernel<<<TOK * HD / 2048 + 1, 256>>>(x, ridx);
    gemm_kernel<0><<<dim3(GUN / NT, 2, NEXP), 256, SMEM0>>>(wgu, bgu);
    requant_kernel<<<ATOT * ID / 2048, 256>>>();
    gemm_kernel<1><<<dim3(HD / NT, 2, NEXP), 256, SMEM1>>>(wdn, bdn);
    combine_kernel<<<TOK * HD / 4 / 256, 256>>>(rw, out);
}

// round 17
// speedup vs baseline: 1.0553x; 1.0553x over previous
#include <cuda_runtime.h>
#include <cuda_fp16.h>
#include <cuda_bf16.h>
#include <cuda_fp8.h>
#include <cstdint>

#define TOK   512
#define HD    2880
#define ID    2880
#define NEXP  8
#define ATOT  1024
#define KD    2880
#define GUN   5760

#define MT    160
#define NT    80
#define NTHR  320
#define KTLE  64
#define NKT   (KD / KTLE)     // 45
#define ASTR  72
#define BSTR  72
#define A_ELEMS (MT * ASTR)   // 11520 halves
#define B_EL    (NT * BSTR)   // 5760 halves per plane

__device__ __align__(16) __nv_bfloat16 g_xdq[TOK * HD];
__device__ __align__(16) __half        g_inter[ATOT * ID];
__device__ __align__(16) float         g_mid[ATOT * ID];
__device__ __align__(16) float         g_y[ATOT * HD];
__device__ int g_list[ATOT];
__device__ int g_pos[ATOT];
__device__ int g_start[NEXP];
__device__ int g_cnt[NEXP];

__device__ __forceinline__ float ceil_pow2_scale(float ds) {
    unsigned i = __float_as_uint(ds);
    i = (i + 0x7FFFFFu) & 0x7F800000u;
    float r = __uint_as_float(i);
    return (r == 0.0f) ? 1.17549435e-38f : r;
}

__device__ __forceinline__ float fp8_qdq(float v, float dsr) {
    float inv = __uint_as_float(0x7F000000u - __float_as_uint(dsr));
    float q = v * inv;
    q = fminf(fmaxf(q, -448.0f), 448.0f);
    __nv_fp8_storage_t s = __nv_cvt_float_to_fp8(q, __NV_SATFINITE, __NV_E4M3);
    __half_raw hr = __nv_cvt_fp8_to_halfraw(s, __NV_E4M3);
    return __half2float(*reinterpret_cast<__half*>(&hr)) * dsr;
}

#define LDSM4(R, ADDR) asm volatile( \
    "ldmatrix.sync.aligned.m8n8.x4.shared.b16 {%0,%1,%2,%3},[%4];" \
    : "=r"((R)[0]), "=r"((R)[1]), "=r"((R)[2]), "=r"((R)[3]) : "r"(ADDR))

#define LDSM2(R, ADDR) asm volatile( \
    "ldmatrix.sync.aligned.m8n8.x2.shared.b16 {%0,%1},[%2];" \
    : "=r"((R)[0]), "=r"((R)[1]) : "r"(ADDR))

#define MMA_IMPL(TYSTR, C, A, B0, B1) asm volatile( \
    "mma.sync.aligned.m16n8k16.row.col.f32." TYSTR ".f32 " \
    "{%0,%1,%2,%3},{%4,%5,%6,%7},{%8,%9},{%0,%1,%2,%3};" \
    : "+f"((C)[0]), "+f"((C)[1]), "+f"((C)[2]), "+f"((C)[3]) \
    : "r"((A)[0]), "r"((A)[1]), "r"((A)[2]), "r"((A)[3]), "r"(B0), "r"(B1))

#define CP_ASYNC16(DST, SRC) asm volatile( \
    "cp.async.cg.shared.global [%0],[%1],16;" :: "r"(DST), "l"(SRC))
#define CP_COMMIT asm volatile("cp.async.commit_group;")
#define CP_WAIT0  asm volatile("cp.async.wait_group 0;" ::: "memory")

// blocks 0..719: quantize x (8 values/thread, 4 lanes per 32-block)
// block 720: routing (256 threads, 4 assignments each)
__global__ void quantx_route_kernel(const float* __restrict__ x,
                                    const int* __restrict__ ridx) {
    if (blockIdx.x < TOK * HD / 2048) {
        int idx = blockIdx.x * 256 + threadIdx.x;
        float4 v0 = *reinterpret_cast<const float4*>(x + (size_t)idx * 8);
        float4 v1 = *reinterpret_cast<const float4*>(x + (size_t)idx * 8 + 4);
        float m = fmaxf(fmaxf(fmaxf(fabsf(v0.x), fabsf(v0.y)), fmaxf(fabsf(v0.z), fabsf(v0.w))),
                        fmaxf(fmaxf(fabsf(v1.x), fabsf(v1.y)), fmaxf(fabsf(v1.z), fabsf(v1.w))));
        #pragma unroll
        for (int o = 2; o; o >>= 1) m = fmaxf(m, __shfl_xor_sync(0xffffffffu, m, o));
        float dsr = ceil_pow2_scale(m / 448.0f);
        __nv_bfloat162 p0, p1, p2, p3;
        p0.x = __float2bfloat16_rn(fp8_qdq(v0.x, dsr));
        p0.y = __float2bfloat16_rn(fp8_qdq(v0.y, dsr));
        p1.x = __float2bfloat16_rn(fp8_qdq(v0.z, dsr));
        p1.y = __float2bfloat16_rn(fp8_qdq(v0.w, dsr));
        p2.x = __float2bfloat16_rn(fp8_qdq(v1.x, dsr));
        p2.y = __float2bfloat16_rn(fp8_qdq(v1.y, dsr));
        p3.x = __float2bfloat16_rn(fp8_qdq(v1.z, dsr));
        p3.y = __float2bfloat16_rn(fp8_qdq(v1.w, dsr));
        *reinterpret_cast<uint4*>((uint16_t*)g_xdq + (size_t)idx * 8) =
            make_uint4(*reinterpret_cast<uint32_t*>(&p0), *reinterpret_cast<uint32_t*>(&p1),
                       *reinterpret_cast<uint32_t*>(&p2), *reinterpret_cast<uint32_t*>(&p3));
    } else {
        __shared__ int cnt[NEXP], off[NEXP];
        int t = threadIdx.x;
        if (t < NEXP) cnt[t] = 0;
        __syncthreads();
        int e[4];
        #pragma unroll
        for (int k = 0; k < 4; k++) {
            e[k] = ridx[t + k * 256];
            atomicAdd(&cnt[e[k]], 1);
        }
        __syncthreads();
        if (t == 0) {
            int s = 0;
            for (int i = 0; i < NEXP; i++) {
                g_start[i] = s; off[i] = s; g_cnt[i] = cnt[i]; s += cnt[i];
            }
        }
        __syncthreads();
        #pragma unroll
        for (int k = 0; k < 4; k++) {
            int p = atomicAdd(&off[e[k]], 1);
            g_list[p] = t + k * 256;
            g_pos[t + k * 256] = p;
        }
    }
}

// 8 values/thread, 4 lanes per 32-block; bit-exact qdq
__global__ void requant_kernel() {
    int idx = blockIdx.x * 256 + threadIdx.x;
    float4 v0 = *reinterpret_cast<const float4*>(g_mid + (size_t)idx * 8);
    float4 v1 = *reinterpret_cast<const float4*>(g_mid + (size_t)idx * 8 + 4);
    float m = fmaxf(fmaxf(fmaxf(fabsf(v0.x), fabsf(v0.y)), fmaxf(fabsf(v0.z), fabsf(v0.w))),
                    fmaxf(fmaxf(fabsf(v1.x), fabsf(v1.y)), fmaxf(fabsf(v1.z), fabsf(v1.w))));
    #pragma unroll
    for (int o = 2; o; o >>= 1) m = fmaxf(m, __shfl_xor_sync(0xffffffffu, m, o));
    float dsr = ceil_pow2_scale(m / 448.0f);
    __half2 p0, p1, p2, p3;
    p0.x = __float2half_rn(fp8_qdq(v0.x, dsr));
    p0.y = __float2half_rn(fp8_qdq(v0.y, dsr));
    p1.x = __float2half_rn(fp8_qdq(v0.z, dsr));
    p1.y = __float2half_rn(fp8_qdq(v0.w, dsr));
    p2.x = __float2half_rn(fp8_qdq(v1.x, dsr));
    p2.y = __float2half_rn(fp8_qdq(v1.y, dsr));
    p3.x = __float2half_rn(fp8_qdq(v1.z, dsr));
    p3.y = __float2half_rn(fp8_qdq(v1.w, dsr));
    *reinterpret_cast<uint4*>((uint16_t*)g_inter + (size_t)idx * 8) =
        make_uint4(*reinterpret_cast<uint32_t*>(&p0), *reinterpret_cast<uint32_t*>(&p1),
                   *reinterpret_cast<uint32_t*>(&p2), *reinterpret_cast<uint32_t*>(&p3));
}

// PHASE 0: gate_up (bf16 hi/lo planes) + swiglu -> g_mid (fp32)
// PHASE 1: down (fp16) + bias -> g_y
// 320 threads, warp grid 5M x 2N; warp tile 32 x 40; MT=160, NT=80, occ 2.
template<int PHASE>
__global__ void __launch_bounds__(NTHR, 2) gemm_kernel(
    const float* __restrict__ Wg, const float* __restrict__ biasg)
{
    constexpr int NTOT = (PHASE == 0) ? GUN : HD;
    constexpr int NPL  = (PHASE == 0) ? 2 : 1;
    constexpr int STG  = A_ELEMS + NPL * B_EL;
    const int nt = blockIdx.x, mt = blockIdx.y, e = blockIdx.z;
    const int cnt = g_cnt[e];
    if (mt * MT >= cnt) return;
    const int start = g_start[e];
    const int n0 = nt * NT;
    const int tid = threadIdx.x;
    const int lane = tid & 31, wid = tid >> 5;
    const int wm = wid % 5, wn = wid / 5;

    extern __shared__ __align__(16) char smem_raw[];
    uint16_t* sm = (uint16_t*)smem_raw;
    uint32_t smemBase = (uint32_t)__cvta_generic_to_shared(sm);
    __shared__ int s_a[MT];

    if (tid < MT) {
        int p = start + mt * MT + tid; if (p > ATOT - 1) p = ATOT - 1;
        s_a[tid] = (PHASE == 0) ? (g_list[p] >> 1) : p;
    }
    __syncthreads();

    const uint16_t* srcA = (PHASE == 0) ? (const uint16_t*)g_xdq
                                        : (const uint16_t*)g_inter;
    const float* W = Wg + (size_t)e * NTOT * KD + (size_t)n0 * KD;

    const int aLdOff = (lane & 15) * ASTR + (lane >> 4) * 8 + wm * 32 * ASTR;
    const int bLd16 = ((lane & 7) + ((lane & 16) ? 8 : 0)) * BSTR +
                      ((lane & 8) ? 8 : 0) + wn * 40 * BSTR;
    const int bLd8  = (lane & 7) * BSTR + ((lane & 8) ? 8 : 0) +
                      (wn * 40 + 32) * BSTR;

    float acc[2][5][4];
    #pragma unroll
    for (int i = 0; i < 2; i++)
        #pragma unroll
        for (int j = 0; j < 5; j++)
            #pragma unroll
            for (int k = 0; k < 4; k++) acc[i][j][k] = 0.0f;

    float4 breg[4];
    auto loadB = [&](int kt) {
        #pragma unroll
        for (int j = 0; j < 4; j++) {
            int chunk = tid + j * NTHR;
            breg[j] = *reinterpret_cast<const float4*>(
                W + (size_t)(chunk >> 4) * KD + kt * KTLE + (chunk & 15) * 4);
        }
    };
    auto cpA = [&](int st, int kt) {
        uint32_t so = smemBase + (uint32_t)(st * STG) * 2;
        #pragma unroll
        for (int i = 0; i < 4; i++) {
            int chunk = tid + i * NTHR;
            int row = chunk >> 3, c16 = chunk & 7;
            const uint16_t* src = srcA + (size_t)s_a[row] * KD + c16 * 8 + kt * KTLE;
            CP_ASYNC16(so + (uint32_t)(row * ASTR + c16 * 8) * 2, src);
        }
        CP_COMMIT;
    };
    auto stsB = [&](int st) {
        uint16_t* bh = sm + st * STG + A_ELEMS;
        #pragma unroll
        for (int j = 0; j < 4; j++) {
            int chunk = tid + j * NTHR;
            int off = (chunk >> 4) * BSTR + (chunk & 15) * 4;
            float f[4] = {breg[j].x, breg[j].y, breg[j].z, breg[j].w};
            if constexpr (PHASE == 0) {
                uint32_t hv[2], lv[2];
                #pragma unroll
                for (int q = 0; q < 2; q++) {
                    __nv_bfloat16 h0 = __float2bfloat16_rn(f[2 * q]);
                    __nv_bfloat16 h1 = __float2bfloat16_rn(f[2 * q + 1]);
                    __nv_bfloat162 hh; hh.x = h0; hh.y = h1;
                    __nv_bfloat162 ll = __floats2bfloat162_rn(
                        f[2 * q]     - __bfloat162float(h0),
                        f[2 * q + 1] - __bfloat162float(h1));
                    hv[q] = *reinterpret_cast<uint32_t*>(&hh);
                    lv[q] = *reinterpret_cast<uint32_t*>(&ll);
                }
                *reinterpret_cast<uint2*>(bh + off)        = make_uint2(hv[0], hv[1]);
                *reinterpret_cast<uint2*>(bh + B_EL + off) = make_uint2(lv[0], lv[1]);
            } else {
                __half2 h0 = __floats2half2_rn(f[0], f[1]);
                __half2 h1 = __floats2half2_rn(f[2], f[3]);
                *reinterpret_cast<uint2*>(bh + off) =
                    make_uint2(*reinterpret_cast<uint32_t*>(&h0),
                               *reinterpret_cast<uint32_t*>(&h1));
            }
        }
    };
    auto compute = [&](int st) {
        uint32_t aB = smemBase + (uint32_t)(st * STG) * 2;
        uint32_t bB = aB + A_ELEMS * 2;
        #pragma unroll
        for (int ks = 0; ks < 4; ks++) {
            uint32_t ar[2][4], b4[2][4], b2[2];
            #pragma unroll
            for (int mf = 0; mf < 2; mf++)
                LDSM4(ar[mf], aB + (uint32_t)(aLdOff + mf * 16 * ASTR + ks * 16) * 2);
            LDSM4(b4[0], bB + (uint32_t)(bLd16 + ks * 16) * 2);
            LDSM4(b4[1], bB + (uint32_t)(bLd16 + 16 * BSTR + ks * 16) * 2);
            LDSM2(b2,    bB + (uint32_t)(bLd8 + ks * 16) * 2);
            #pragma unroll
            for (int mf = 0; mf < 2; mf++) {
                #pragma unroll
                for (int nf = 0; nf < 4; nf++) {
                    int ng = nf >> 1, pr = nf & 1;
                    if constexpr (PHASE == 0)
                        MMA_IMPL("bf16.bf16", acc[mf][nf], ar[mf], b4[ng][2*pr], b4[ng][2*pr+1]);
                    else
                        MMA_IMPL("f16.f16",   acc[mf][nf], ar[mf], b4[ng][2*pr], b4[ng][2*pr+1]);
                }
                if constexpr (PHASE == 0)
                    MMA_IMPL("bf16.bf16", acc[mf][4], ar[mf], b2[0], b2[1]);
                else
                    MMA_IMPL("f16.f16",   acc[mf][4], ar[mf], b2[0], b2[1]);
            }
            if constexpr (PHASE == 0) {
                uint32_t lB = bB + B_EL * 2;
                LDSM4(b4[0], lB + (uint32_t)(bLd16 + ks * 16) * 2);
                LDSM4(b4[1], lB + (uint32_t)(bLd16 + 16 * BSTR + ks * 16) * 2);
                LDSM2(b2,    lB + (uint32_t)(bLd8 + ks * 16) * 2);
                #pragma unroll
                for (int mf = 0; mf < 2; mf++) {
                    #pragma unroll
                    for (int nf = 0; nf < 4; nf++) {
                        int ng = nf >> 1, pr = nf & 1;
                        MMA_IMPL("bf16.bf16", acc[mf][nf], ar[mf], b4[ng][2*pr], b4[ng][2*pr+1]);
                    }
                    MMA_IMPL("bf16.bf16", acc[mf][4], ar[mf], b2[0], b2[1]);
                }
            }
        }
    };

    loadB(0);
    cpA(0, 0);
    stsB(0);
    CP_WAIT0;
    __syncthreads();
    for (int kt = 0; kt < NKT; kt++) {
        int nk = kt + 1;
        if (nk < NKT) { loadB(nk); cpA(nk & 1, nk); }
        compute(kt & 1);
        if (nk < NKT) { stsB(nk & 1); CP_WAIT0; }
        __syncthreads();
    }

    const int remain = cnt - mt * MT;
    const float* bias = biasg + (size_t)e * NTOT;

    if constexpr (PHASE == 0) {
        #pragma unroll
        for (int mf = 0; mf < 2; mf++)
            #pragma unroll
            for (int nf = 0; nf < 5; nf++) {
                int gl = wn * 40 + nf * 8 + 2 * (lane & 3);
                float bg = bias[n0 + gl], bu = bias[n0 + gl + 1];
                int icol = nt * 40 + wn * 20 + nf * 4 + (lane & 3);
                #pragma unroll
                for (int h = 0; h < 2; h++) {
                    int r = wm * 32 + mf * 16 + (lane >> 2) + h * 8;
                    if (r < remain) {
                        float gate = acc[mf][nf][2 * h] + bg;
                        float up   = acc[mf][nf][2 * h + 1] + bu;
                        gate = fminf(gate, 7.0f);
                        up = fminf(fmaxf(up, -7.0f), 7.0f);
                        float sig = 1.0f / (1.0f + expf(-1.702f * gate));
                        g_mid[(size_t)(start + mt * MT + r) * ID + icol] =
                            gate * sig * (up + 1.0f);
                    }
                }
            }
    } else {
        #pragma unroll
        for (int mf = 0; mf < 2; mf++)
            #pragma unroll
            for (int nf = 0; nf < 5; nf++) {
                int col = n0 + wn * 40 + nf * 8 + 2 * (lane & 3);
                float b0 = bias[col], b1 = bias[col + 1];
                #pragma unroll
                for (int h = 0; h < 2; h++) {
                    int r = wm * 32 + mf * 16 + (lane >> 2) + h * 8;
                    if (r < remain) {
                        float* dst = g_y + (size_t)(start + mt * MT + r) * HD + col;
                        dst[0] = acc[mf][nf][2 * h]     + b0;
                        dst[1] = acc[mf][nf][2 * h + 1] + b1;
                    }
                }
            }
    }
}

// float4 combine: 4 consecutive columns per thread
__global__ void combine_kernel(const float* __restrict__ rw, float* __restrict__ out) {
    int idx = blockIdx.x * 256 + threadIdx.x;   // over TOK * (HD/4)
    int t = idx / (HD / 4);
    int c4 = (idx % (HD / 4)) * 4;
    int a0 = 2 * t, a1 = 2 * t + 1;
    float w0 = rw[a0], w1 = rw[a1];
    const float4 v0 = *reinterpret_cast<const float4*>(
        g_y + (size_t)g_pos[a0] * HD + c4);
    const float4 v1 = *reinterpret_cast<const float4*>(
        g_y + (size_t)g_pos[a1] * HD + c4);
    float4 o;
    o.x = w0 * v0.x + w1 * v1.x;
    o.y = w0 * v0.y + w1 * v1.y;
    o.z = w0 * v0.z + w1 * v1.z;
    o.w = w0 * v0.w + w1 * v1.w;
    *reinterpret_cast<float4*>(out + (size_t)t * HD + c4) = o;
}

#define SMEM0 (2 * (A_ELEMS + 2 * B_EL) * 2)   // 92160
#define SMEM1 (2 * (A_ELEMS + 1 * B_EL) * 2)   // 69120

extern "C" void kernel_launch(void* const* d_in, const int* in_sizes, int n_in,
                              void* d_out, int out_size) {
    const float* x    = (const float*)d_in[0];
    const int*   ridx = (const int*)d_in[1];
    const float* rw   = (const float*)d_in[2];
    const float* wgu  = (const float*)d_in[3];
    const float* bgu  = (const float*)d_in[4];
    const float* wdn  = (const float*)d_in[5];
    const float* bdn  = (const float*)d_in[6];
    float* out = (float*)d_out;

    cudaFuncSetAttribute(gemm_kernel<0>, cudaFuncAttributeMaxDynamicSharedMemorySize, SMEM0);
    cudaFuncSetAttribute(gemm_kernel<1>, cudaFuncAttributeMaxDynamicSharedMemorySize, SMEM1);

    quantx_route_kernel<<<TOK * HD / 2048 + 1, 256>>>(x, ridx);
    gemm_kernel<0><<<dim3(GUN / NT, 2, NEXP), NTHR, SMEM0>>>(wgu, bgu);
    requant_kernel<<<ATOT * ID / 2048, 256>>>();
    gemm_kernel<1><<<dim3(HD / NT, 2, NEXP), NTHR, SMEM1>>>(wdn, bdn);
    combine_kernel<<<TOK * HD / 4 / 256, 256>>>(rw, out);
}